// round 13
// baseline (speedup 1.0000x reference)
#include <cuda_runtime.h>

#define DD  1024
#define BB  128
#define LLn 196
#define LP1 197

// ---------------- scratch (no allocs allowed) ----------------
__device__ float g_fr [BB*DD];
__device__ float g_fre[BB*DD];
__device__ float g_ho [BB*DD];
__device__ float g_hoe[BB*DD];
__device__ float g_att[BB*DD];
__device__ float g_scores[BB*LP1];
__device__ float g_part[8][BB*DD];   // GEMM K-split partials

// ---------------- helpers ----------------
__device__ __forceinline__ unsigned long long fma2(unsigned long long a,
                                                   unsigned long long b,
                                                   unsigned long long c) {
    unsigned long long r;
    asm("fma.rn.f32x2 %0, %1, %2, %3;" : "=l"(r) : "l"(a), "l"(b), "l"(c));
    return r;
}
__device__ __forceinline__ unsigned long long dup2(float x) {
    unsigned long long r;
    asm("mov.b64 %0, {%1, %1};" : "=l"(r) : "f"(x));
    return r;
}
__device__ __forceinline__ float tanh_fast(float x) {
    float y;
    asm("tanh.approx.f32 %0, %1;" : "=f"(y) : "f"(x));
    return y;
}

// ---------------- GEMM partial: P = A[:,ks] @ W[:,ks]^T ----------------
// BM=64, BN=128, BK=16, 256 threads (2 warps/SMSP).
// Thread tile: 4 m-rows x 8 n-cols as n-PAIRS (u64 acc) -> B consumed as
// natural u64 from LDS (no B dup); A scalar duplicated (4 dup2/k).
// Thread n-cols: [tx*4, tx*4+3] and [64+tx*4, 64+tx*4+3] (conflict-free).
// grid (8, 2, z): prob = z / ks_per_prob, koff = (z % ks_per_prob) * klen.
__global__ void __launch_bounds__(256)
gemm_kernel(const float* __restrict__ A0, const float* __restrict__ W0,
            const float* __restrict__ A1, const float* __restrict__ W1,
            int ks_per_prob, int klen)
{
    const int bz = blockIdx.z;
    const float* A = (bz < ks_per_prob) ? A0 : A1;
    const float* W = (bz < ks_per_prob) ? W0 : W1;
    const int koff = (bz % ks_per_prob) * klen;
    float* P = g_part[bz];

    __shared__ float As[2][16][72];           // 64 rows + pad
    __shared__ float Bs[2][16][132];          // 128 rows + pad

    const int t  = threadIdx.x;
    const int bn = blockIdx.x << 7;
    const int bm = blockIdx.y << 6;

    const int lrA = t >> 2, lcA = (t & 3) << 2;   // A: row 0..63, 1 float4
    const int lrB = t >> 1, lcB = (t & 1) << 3;   // B: row 0..127, 2 float4
    const float* Ap = A + (size_t)(bm + lrA) * DD + koff + lcA;
    const float* Wp = W + (size_t)(bn + lrB) * DD + koff + lcB;

    const int tx = t & 15, ty = t >> 4;
    const int m0 = ty << 2, n0 = tx << 2;

    unsigned long long acc[4][4];   // [m][n-pair]: j<2 -> n0+2j..; j>=2 -> 64+n0+2(j-2)..
#pragma unroll
    for (int i = 0; i < 4; i++)
#pragma unroll
        for (int j = 0; j < 4; j++) acc[i][j] = 0ull;

    float4 av  = *(const float4*)Ap;
    float4 wv0 = *(const float4*)Wp;
    float4 wv1 = *(const float4*)(Wp + 4);

    {
        float a[4] = {av.x, av.y, av.z, av.w};
        float w[8] = {wv0.x, wv0.y, wv0.z, wv0.w, wv1.x, wv1.y, wv1.z, wv1.w};
#pragma unroll
        for (int i = 0; i < 4; i++) As[0][lcA + i][lrA] = a[i];
#pragma unroll
        for (int i = 0; i < 8; i++) Bs[0][lcB + i][lrB] = w[i];
    }
    __syncthreads();

    const int nkb = klen >> 4;
    int buf = 0;
#pragma unroll 1
    for (int kb = 0; kb < nkb; kb++) {
        if (kb < nkb - 1) {
            av  = *(const float4*)(Ap + (kb + 1) * 16);
            wv0 = *(const float4*)(Wp + (kb + 1) * 16);
            wv1 = *(const float4*)(Wp + (kb + 1) * 16 + 4);
        }
#pragma unroll
        for (int k = 0; k < 16; k++) {
            float4 am4 = *(const float4*)&As[buf][k][m0];       // broadcast
            union { float4 v; unsigned long long u[2]; } b0, b1;
            b0.v = *(const float4*)&Bs[buf][k][n0];             // contig 256B/warp
            b1.v = *(const float4*)&Bs[buf][k][n0 + 64];        // contig 256B/warp
            unsigned long long ad[4] = { dup2(am4.x), dup2(am4.y),
                                         dup2(am4.z), dup2(am4.w) };
#pragma unroll
            for (int i = 0; i < 4; i++) {
                acc[i][0] = fma2(ad[i], b0.u[0], acc[i][0]);
                acc[i][1] = fma2(ad[i], b0.u[1], acc[i][1]);
                acc[i][2] = fma2(ad[i], b1.u[0], acc[i][2]);
                acc[i][3] = fma2(ad[i], b1.u[1], acc[i][3]);
            }
        }
        if (kb < nkb - 1) {
            const int nb = buf ^ 1;
            float a[4] = {av.x, av.y, av.z, av.w};
            float w[8] = {wv0.x, wv0.y, wv0.z, wv0.w, wv1.x, wv1.y, wv1.z, wv1.w};
#pragma unroll
            for (int i = 0; i < 4; i++) As[nb][lcA + i][lrA] = a[i];
#pragma unroll
            for (int i = 0; i < 8; i++) Bs[nb][lcB + i][lrB] = w[i];
            __syncthreads();
            buf = nb;
        }
    }

    // epilogue: acc[i][*] are the output pairs in-place -> direct 16B stores
#pragma unroll
    for (int i = 0; i < 4; i++) {
        float* r = P + (size_t)(bm + m0 + i) * DD + bn;
        ulonglong2 lo; lo.x = acc[i][0]; lo.y = acc[i][1];
        ulonglong2 hi; hi.x = acc[i][2]; hi.y = acc[i][3];
        *(ulonglong2*)(r + n0)      = lo;
        *(ulonglong2*)(r + 64 + n0) = hi;
    }
}

// ---------------- combine4: dst = act(sum of 4 partials + bias), 2 problems ----
// grid (64, 2), 256 threads, 2 float4 per thread (8 LDGs in flight).
__global__ void __launch_bounds__(256)
combine4_kernel(float* __restrict__ dst0, const float* __restrict__ bias0, int act0,
                float* __restrict__ dst1, const float* __restrict__ bias1, int act1)
{
    const int p = blockIdx.y;
    float* dst        = p ? dst1  : dst0;
    const float* bias = p ? bias1 : bias0;
    const int act     = p ? act1  : act0;

    const int base = blockIdx.x * 512 + threadIdx.x;
#pragma unroll
    for (int h = 0; h < 2; h++) {
        const int idx = base + h * 256;
        float4 a = ((const float4*)g_part[4*p    ])[idx];
        float4 b = ((const float4*)g_part[4*p + 1])[idx];
        float4 cc = ((const float4*)g_part[4*p + 2])[idx];
        float4 d = ((const float4*)g_part[4*p + 3])[idx];
        float4 bi = ((const float4*)bias)[idx & 255];

        float o[4] = { (a.x + b.x) + (cc.x + d.x) + bi.x,
                       (a.y + b.y) + (cc.y + d.y) + bi.y,
                       (a.z + b.z) + (cc.z + d.z) + bi.z,
                       (a.w + b.w) + (cc.w + d.w) + bi.w };
        if (act == 1) {
#pragma unroll
            for (int j = 0; j < 4; j++) o[j] = fmaxf(o[j], 0.0f);
        } else if (act == 2) {
#pragma unroll
            for (int j = 0; j < 4; j++) o[j] = tanhf(o[j]);
        }
        ((float4*)dst)[idx] = make_float4(o[0], o[1], o[2], o[3]);
    }
}

// ---------------- combine8: dst = tanh(sum of 8 partials + bias) ----------------
__global__ void __launch_bounds__(256)
combine8_kernel(float* __restrict__ dst, const float* __restrict__ bias)
{
    const int base = blockIdx.x * 512 + threadIdx.x;
#pragma unroll
    for (int h = 0; h < 2; h++) {
        const int idx = base + h * 256;
        float s[4] = {0.f, 0.f, 0.f, 0.f};
#pragma unroll
        for (int q = 0; q < 8; q++) {
            float4 a = ((const float4*)g_part[q])[idx];
            s[0] += a.x; s[1] += a.y; s[2] += a.z; s[3] += a.w;
        }
        float4 bi = ((const float4*)bias)[idx & 255];
        ((float4*)dst)[idx] = make_float4(tanhf(s[0] + bi.x), tanhf(s[1] + bi.y),
                                          tanhf(s[2] + bi.z), tanhf(s[3] + bi.w));
    }
}

// ---------------- scores[b,l] = Wa . tanh(E[b,l,:] + hoe[b,:]) + ba ----------------
// One warp per l, contiguous float4 per lane. grid (25, 128), 256 threads.
__global__ void __launch_bounds__(256)
scores_kernel(const float* __restrict__ embed,
              const float* __restrict__ Wa, const float* __restrict__ ba)
{
    const int b    = blockIdx.y;
    const int t    = threadIdx.x;
    const int w    = t >> 5;
    const int lane = t & 31;
    const int l    = blockIdx.x * 8 + w;
    if (l >= LP1) return;

    const float* row  = (l == 0) ? (g_fre + (size_t)b * DD)
                                 : (embed + ((size_t)b * LLn + (l - 1)) * DD);
    const float* hrow = g_hoe + (size_t)b * DD;

    float acc = 0.0f;
#pragma unroll
    for (int p = 0; p < 8; p++) {
        const int d = p * 128 + lane * 4;
        float4 e = *(const float4*)(row  + d);
        float4 h = *(const float4*)(hrow + d);
        float4 v = *(const float4*)(Wa   + d);
        acc = fmaf(tanh_fast(e.x + h.x), v.x, acc);
        acc = fmaf(tanh_fast(e.y + h.y), v.y, acc);
        acc = fmaf(tanh_fast(e.z + h.z), v.z, acc);
        acc = fmaf(tanh_fast(e.w + h.w), v.w, acc);
    }
#pragma unroll
    for (int o = 16; o; o >>= 1) acc += __shfl_xor_sync(0xffffffffu, acc, o);
    if (lane == 0) g_scores[b * LP1 + l] = acc + ba[0];
}

// ---------------- fused softmax + weighted sum ----------------
__global__ void __launch_bounds__(256)
wsum_kernel(const float* __restrict__ conv)
{
    const int s = blockIdx.x, b = blockIdx.y, t = threadIdx.x;
    __shared__ float  sp[LP1];
    __shared__ float  red[8];
    __shared__ float4 red4[4][64];

    float v = (t < LP1) ? g_scores[b * LP1 + t] : -3.4e38f;
    float m = v;
#pragma unroll
    for (int o = 16; o; o >>= 1) m = fmaxf(m, __shfl_xor_sync(0xffffffffu, m, o));
    if ((t & 31) == 0) red[t >> 5] = m;
    __syncthreads();
    float mx = red[0];
#pragma unroll
    for (int i = 1; i < 8; i++) mx = fmaxf(mx, red[i]);
    __syncthreads();

    float e = (t < LP1) ? expf(v - mx) : 0.0f;
    float su = e;
#pragma unroll
    for (int o = 16; o; o >>= 1) su += __shfl_xor_sync(0xffffffffu, su, o);
    if ((t & 31) == 0) red[t >> 5] = su;
    __syncthreads();
    float tot = red[0] + red[1] + red[2] + red[3]
              + red[4] + red[5] + red[6] + red[7];
    if (t < LP1) sp[t] = e / tot;
    __syncthreads();

    const int c  = t & 63;
    const int lg = t >> 6;
    const int d0 = (s << 8) + (c << 2);
    const float* base = conv + (size_t)b * LLn * DD + d0;

    float4 acc = make_float4(0.f, 0.f, 0.f, 0.f);
    const int l0 = lg * 49;
#pragma unroll 1
    for (int u = 0; u < 12; u++) {
        const int l = l0 + (u << 2);
        float4 v0 = *(const float4*)(base + (size_t)(l + 0) * DD);
        float4 v1 = *(const float4*)(base + (size_t)(l + 1) * DD);
        float4 v2 = *(const float4*)(base + (size_t)(l + 2) * DD);
        float4 v3 = *(const float4*)(base + (size_t)(l + 3) * DD);
        float w0 = sp[l + 1], w1 = sp[l + 2], w2 = sp[l + 3], w3 = sp[l + 4];
        acc.x += v0.x*w0 + v1.x*w1 + v2.x*w2 + v3.x*w3;
        acc.y += v0.y*w0 + v1.y*w1 + v2.y*w2 + v3.y*w3;
        acc.z += v0.z*w0 + v1.z*w1 + v2.z*w2 + v3.z*w3;
        acc.w += v0.w*w0 + v1.w*w1 + v2.w*w2 + v3.w*w3;
    }
    {
        const int l = l0 + 48;
        float4 v0 = *(const float4*)(base + (size_t)l * DD);
        float w0 = sp[l + 1];
        acc.x += v0.x*w0; acc.y += v0.y*w0; acc.z += v0.z*w0; acc.w += v0.w*w0;
    }
    red4[lg][c] = acc;
    __syncthreads();

    if (lg == 0) {
        float4 r0 = red4[0][c], r1 = red4[1][c], r2 = red4[2][c], r3 = red4[3][c];
        float4 f = *(const float4*)(g_fr + (size_t)b * DD + d0);
        float4 h = *(const float4*)(g_ho + (size_t)b * DD + d0);
        float p0 = sp[0];
        float4 o;
        o.x = r0.x + r1.x + r2.x + r3.x + f.x * p0 + h.x;
        o.y = r0.y + r1.y + r2.y + r3.y + f.y * p0 + h.y;
        o.z = r0.z + r1.z + r2.z + r3.z + f.z * p0 + h.z;
        o.w = r0.w + r1.w + r2.w + r3.w + f.w * p0 + h.w;
        *(float4*)(g_att + (size_t)b * DD + d0) = o;
    }
}

// ---------------- host launcher ----------------
extern "C" void kernel_launch(void* const* d_in, const int* in_sizes, int n_in,
                              void* d_out, int out_size)
{
    (void)in_sizes; (void)n_in; (void)out_size;
    const float* h_out = (const float*)d_in[0];
    const float* fake  = (const float*)d_in[1];
    const float* conv  = (const float*)d_in[2];
    const float* embed = (const float*)d_in[3];
    const float* W_fr  = (const float*)d_in[4];
    const float* b_fr  = (const float*)d_in[5];
    const float* W_fre = (const float*)d_in[6];
    const float* b_fre = (const float*)d_in[7];
    const float* W_ho  = (const float*)d_in[8];
    const float* b_ho  = (const float*)d_in[9];
    const float* W_hoe = (const float*)d_in[10];
    const float* b_hoe = (const float*)d_in[11];
    const float* W_a   = (const float*)d_in[12];
    const float* b_a   = (const float*)d_in[13];
    const float* W_h   = (const float*)d_in[14];
    const float* b_h   = (const float*)d_in[15];

    float *fr, *fre, *ho, *hoe, *att;
    cudaGetSymbolAddress((void**)&fr,  g_fr);
    cudaGetSymbolAddress((void**)&fre, g_fre);
    cudaGetSymbolAddress((void**)&ho,  g_ho);
    cudaGetSymbolAddress((void**)&hoe, g_hoe);
    cudaGetSymbolAddress((void**)&att, g_att);

    // stage 1: fr = relu(fake@W_fr^T + b), ho = tanh(h_out@W_ho^T + b)
    gemm_kernel<<<dim3(8, 2, 8), 256>>>(fake, W_fr, h_out, W_ho, 4, 256);
    combine4_kernel<<<dim3(64, 2), 256>>>(fr, b_fr, 1, ho, b_ho, 2);
    // stage 2: fre = fr@W_fre^T + b, hoe = ho@W_hoe^T + b
    gemm_kernel<<<dim3(8, 2, 8), 256>>>(fr, W_fre, ho, W_hoe, 4, 256);
    combine4_kernel<<<dim3(64, 2), 256>>>(fre, b_fre, 0, hoe, b_hoe, 0);
    // attention
    scores_kernel<<<dim3(25, BB), 256>>>(embed, W_a, b_a);
    wsum_kernel<<<dim3(4, BB), 256>>>(conv);
    // stage 3: h = tanh(att@W_h^T + b_h), full-chip ksplit=8
    gemm_kernel<<<dim3(8, 2, 8), 256>>>(att, W_h, att, W_h, 8, 128);
    combine8_kernel<<<dim3(64, 1), 256>>>((float*)d_out, b_h);
}

// round 14
// speedup vs baseline: 1.2346x; 1.2346x over previous
#include <cuda_runtime.h>

#define DD  1024
#define BB  128
#define LLn 196
#define LP1 197

// ---------------- scratch (no allocs allowed) ----------------
__device__ float g_fr [BB*DD];
__device__ float g_fre[BB*DD];
__device__ float g_ho [BB*DD];
__device__ float g_hoe[BB*DD];
__device__ float g_att[BB*DD];
__device__ float g_scores[BB*LP1];
__device__ float g_part[16][BB*DD];  // GEMM K-split partials

// ---------------- helpers ----------------
__device__ __forceinline__ unsigned long long fma2(unsigned long long a,
                                                   unsigned long long b,
                                                   unsigned long long c) {
    unsigned long long r;
    asm("fma.rn.f32x2 %0, %1, %2, %3;" : "=l"(r) : "l"(a), "l"(b), "l"(c));
    return r;
}
__device__ __forceinline__ unsigned long long dup2(float x) {
    unsigned long long r;
    asm("mov.b64 %0, {%1, %1};" : "=l"(r) : "f"(x));
    return r;
}
__device__ __forceinline__ float tanh_fast(float x) {
    float y;
    asm("tanh.approx.f32 %0, %1;" : "=f"(y) : "f"(x));
    return y;
}

// ---------------- GEMM partial: P = A[:,ks] @ W[:,ks]^T ----------------
// BM=128 (full M), BN=128, BK=16, 256 threads (2 warps/SMSP).
// Thread tile 8m x 8n: m-paired u64 accumulators (R12 structure, doubled m).
// Thread n-cols: [tx*4, tx*4+3] and [64+tx*4, ...] (conflict-free LDS).
// grid (8, 1, z): prob = z / ks_per_prob, koff = (z % ks_per_prob) * klen.
__global__ void __launch_bounds__(256)
gemm_kernel(const float* __restrict__ A0, const float* __restrict__ W0,
            const float* __restrict__ A1, const float* __restrict__ W1,
            int ks_per_prob, int klen)
{
    const int bz = blockIdx.z;
    const float* A = (bz < ks_per_prob) ? A0 : A1;
    const float* W = (bz < ks_per_prob) ? W0 : W1;
    const int koff = (bz % ks_per_prob) * klen;
    float* P = g_part[bz];

    __shared__ float As[2][16][136];          // 128 rows + pad
    __shared__ float Bs[2][16][136];          // 128 rows + pad

    const int t  = threadIdx.x;
    const int bn = blockIdx.x << 7;

    const int lr = t >> 1, lc = (t & 1) << 3;     // loader: row 0..127, 2 float4
    const float* Ap = A + (size_t)lr * DD + koff + lc;
    const float* Wp = W + (size_t)(bn + lr) * DD + koff + lc;

    const int tx = t & 15, ty = t >> 4;
    const int m0 = ty << 3, n0 = tx << 2;

    unsigned long long acc[4][8];   // [m-pair][n]: j<4 -> bn+n0+j ; j>=4 -> bn+64+n0+j-4
#pragma unroll
    for (int i = 0; i < 4; i++)
#pragma unroll
        for (int j = 0; j < 8; j++) acc[i][j] = 0ull;

    float4 a0 = *(const float4*)Ap;
    float4 a1 = *(const float4*)(Ap + 4);
    float4 w0 = *(const float4*)Wp;
    float4 w1 = *(const float4*)(Wp + 4);

    {
        float a[8] = {a0.x,a0.y,a0.z,a0.w,a1.x,a1.y,a1.z,a1.w};
        float w[8] = {w0.x,w0.y,w0.z,w0.w,w1.x,w1.y,w1.z,w1.w};
#pragma unroll
        for (int i = 0; i < 8; i++) { As[0][lc+i][lr] = a[i]; Bs[0][lc+i][lr] = w[i]; }
    }
    __syncthreads();

    const int nkb = klen >> 4;
    int buf = 0;
#pragma unroll 1
    for (int kb = 0; kb < nkb; kb++) {
        if (kb < nkb - 1) {
            a0 = *(const float4*)(Ap + (kb + 1) * 16);
            a1 = *(const float4*)(Ap + (kb + 1) * 16 + 4);
            w0 = *(const float4*)(Wp + (kb + 1) * 16);
            w1 = *(const float4*)(Wp + (kb + 1) * 16 + 4);
        }
#pragma unroll
        for (int k = 0; k < 16; k++) {
            union { float4 v; unsigned long long u[2]; } am0, am1;
            am0.v = *(const float4*)&As[buf][k][m0];        // m-pairs (m0,m0+1),(m0+2,m0+3)
            am1.v = *(const float4*)&As[buf][k][m0 + 4];    // m-pairs (m0+4,..),(m0+6,..)
            float4 b0 = *(const float4*)&Bs[buf][k][n0];        // contig 256B/warp
            float4 b1 = *(const float4*)&Bs[buf][k][n0 + 64];   // contig 256B/warp
            unsigned long long bd[8] = {
                dup2(b0.x), dup2(b0.y), dup2(b0.z), dup2(b0.w),
                dup2(b1.x), dup2(b1.y), dup2(b1.z), dup2(b1.w) };
            unsigned long long am[4] = { am0.u[0], am0.u[1], am1.u[0], am1.u[1] };
#pragma unroll
            for (int i = 0; i < 4; i++)
#pragma unroll
                for (int j = 0; j < 8; j++)
                    acc[i][j] = fma2(am[i], bd[j], acc[i][j]);
        }
        if (kb < nkb - 1) {
            const int nb = buf ^ 1;
            float a[8] = {a0.x,a0.y,a0.z,a0.w,a1.x,a1.y,a1.z,a1.w};
            float w[8] = {w0.x,w0.y,w0.z,w0.w,w1.x,w1.y,w1.z,w1.w};
#pragma unroll
            for (int i = 0; i < 8; i++) { As[nb][lc+i][lr] = a[i]; Bs[nb][lc+i][lr] = w[i]; }
            __syncthreads();
            buf = nb;
        }
    }

    // epilogue: acc[i][j] holds rows (m0+2i, m0+2i+1); j<4 -> col bn+n0+j, j>=4 -> bn+64+n0+j-4
#pragma unroll
    for (int i = 0; i < 4; i++) {
        float4 lo0, lo1, hi0, hi1;
        union { unsigned long long u; float f[2]; } c;
        c.u = acc[i][0]; lo0.x = c.f[0]; hi0.x = c.f[1];
        c.u = acc[i][1]; lo0.y = c.f[0]; hi0.y = c.f[1];
        c.u = acc[i][2]; lo0.z = c.f[0]; hi0.z = c.f[1];
        c.u = acc[i][3]; lo0.w = c.f[0]; hi0.w = c.f[1];
        c.u = acc[i][4]; lo1.x = c.f[0]; hi1.x = c.f[1];
        c.u = acc[i][5]; lo1.y = c.f[0]; hi1.y = c.f[1];
        c.u = acc[i][6]; lo1.z = c.f[0]; hi1.z = c.f[1];
        c.u = acc[i][7]; lo1.w = c.f[0]; hi1.w = c.f[1];
        float* r0 = P + (size_t)(m0 + 2*i)     * DD + bn;
        float* r1 = P + (size_t)(m0 + 2*i + 1) * DD + bn;
        *(float4*)(r0 + n0)      = lo0;  *(float4*)(r0 + 64 + n0) = lo1;
        *(float4*)(r1 + n0)      = hi0;  *(float4*)(r1 + 64 + n0) = hi1;
    }
}

// ---------------- combine8x2: dst = act(sum of 8 partials + bias), 2 problems ----
// grid (256, 2), 128 threads, 1 float4 per thread.
__global__ void __launch_bounds__(128)
combine8x2_kernel(float* __restrict__ dst0, const float* __restrict__ bias0, int act0,
                  float* __restrict__ dst1, const float* __restrict__ bias1, int act1)
{
    const int p = blockIdx.y;
    float* dst        = p ? dst1  : dst0;
    const float* bias = p ? bias1 : bias0;
    const int act     = p ? act1  : act0;

    const int idx = blockIdx.x * 128 + threadIdx.x;
    float4 bi = ((const float4*)bias)[idx & 255];
    float s[4] = { bi.x, bi.y, bi.z, bi.w };
#pragma unroll
    for (int q = 0; q < 8; q++) {
        float4 a = ((const float4*)g_part[8*p + q])[idx];
        s[0] += a.x; s[1] += a.y; s[2] += a.z; s[3] += a.w;
    }
    if (act == 1) {
#pragma unroll
        for (int j = 0; j < 4; j++) s[j] = fmaxf(s[j], 0.0f);
    } else if (act == 2) {
#pragma unroll
        for (int j = 0; j < 4; j++) s[j] = tanhf(s[j]);
    }
    ((float4*)dst)[idx] = make_float4(s[0], s[1], s[2], s[3]);
}

// ---------------- combine16: dst = tanh(sum of 16 partials + bias) ----------------
__global__ void __launch_bounds__(128)
combine16_kernel(float* __restrict__ dst, const float* __restrict__ bias)
{
    const int idx = blockIdx.x * 128 + threadIdx.x;
    float4 bi = ((const float4*)bias)[idx & 255];
    float s[4] = { bi.x, bi.y, bi.z, bi.w };
#pragma unroll
    for (int q = 0; q < 16; q++) {
        float4 a = ((const float4*)g_part[q])[idx];
        s[0] += a.x; s[1] += a.y; s[2] += a.z; s[3] += a.w;
    }
    ((float4*)dst)[idx] = make_float4(tanhf(s[0]), tanhf(s[1]),
                                      tanhf(s[2]), tanhf(s[3]));
}

// ---------------- scores[b,l] = Wa . tanh(E[b,l,:] + hoe[b,:]) + ba ----------------
// One warp per l, contiguous float4 per lane. grid (25, 128), 256 threads.
__global__ void __launch_bounds__(256)
scores_kernel(const float* __restrict__ embed,
              const float* __restrict__ Wa, const float* __restrict__ ba)
{
    const int b    = blockIdx.y;
    const int t    = threadIdx.x;
    const int w    = t >> 5;
    const int lane = t & 31;
    const int l    = blockIdx.x * 8 + w;
    if (l >= LP1) return;

    const float* row  = (l == 0) ? (g_fre + (size_t)b * DD)
                                 : (embed + ((size_t)b * LLn + (l - 1)) * DD);
    const float* hrow = g_hoe + (size_t)b * DD;

    float acc = 0.0f;
#pragma unroll
    for (int p = 0; p < 8; p++) {
        const int d = p * 128 + lane * 4;
        float4 e = *(const float4*)(row  + d);
        float4 h = *(const float4*)(hrow + d);
        float4 v = *(const float4*)(Wa   + d);
        acc = fmaf(tanh_fast(e.x + h.x), v.x, acc);
        acc = fmaf(tanh_fast(e.y + h.y), v.y, acc);
        acc = fmaf(tanh_fast(e.z + h.z), v.z, acc);
        acc = fmaf(tanh_fast(e.w + h.w), v.w, acc);
    }
#pragma unroll
    for (int o = 16; o; o >>= 1) acc += __shfl_xor_sync(0xffffffffu, acc, o);
    if (lane == 0) g_scores[b * LP1 + l] = acc + ba[0];
}

// ---------------- fused softmax + weighted sum ----------------
__global__ void __launch_bounds__(256)
wsum_kernel(const float* __restrict__ conv)
{
    const int s = blockIdx.x, b = blockIdx.y, t = threadIdx.x;
    __shared__ float  sp[LP1];
    __shared__ float  red[8];
    __shared__ float4 red4[4][64];

    float v = (t < LP1) ? g_scores[b * LP1 + t] : -3.4e38f;
    float m = v;
#pragma unroll
    for (int o = 16; o; o >>= 1) m = fmaxf(m, __shfl_xor_sync(0xffffffffu, m, o));
    if ((t & 31) == 0) red[t >> 5] = m;
    __syncthreads();
    float mx = red[0];
#pragma unroll
    for (int i = 1; i < 8; i++) mx = fmaxf(mx, red[i]);
    __syncthreads();

    float e = (t < LP1) ? expf(v - mx) : 0.0f;
    float su = e;
#pragma unroll
    for (int o = 16; o; o >>= 1) su += __shfl_xor_sync(0xffffffffu, su, o);
    if ((t & 31) == 0) red[t >> 5] = su;
    __syncthreads();
    float tot = red[0] + red[1] + red[2] + red[3]
              + red[4] + red[5] + red[6] + red[7];
    if (t < LP1) sp[t] = e / tot;
    __syncthreads();

    const int c  = t & 63;
    const int lg = t >> 6;
    const int d0 = (s << 8) + (c << 2);
    const float* base = conv + (size_t)b * LLn * DD + d0;

    float4 acc = make_float4(0.f, 0.f, 0.f, 0.f);
    const int l0 = lg * 49;
#pragma unroll 1
    for (int u = 0; u < 12; u++) {
        const int l = l0 + (u << 2);
        float4 v0 = *(const float4*)(base + (size_t)(l + 0) * DD);
        float4 v1 = *(const float4*)(base + (size_t)(l + 1) * DD);
        float4 v2 = *(const float4*)(base + (size_t)(l + 2) * DD);
        float4 v3 = *(const float4*)(base + (size_t)(l + 3) * DD);
        float w0 = sp[l + 1], w1 = sp[l + 2], w2 = sp[l + 3], w3 = sp[l + 4];
        acc.x += v0.x*w0 + v1.x*w1 + v2.x*w2 + v3.x*w3;
        acc.y += v0.y*w0 + v1.y*w1 + v2.y*w2 + v3.y*w3;
        acc.z += v0.z*w0 + v1.z*w1 + v2.z*w2 + v3.z*w3;
        acc.w += v0.w*w0 + v1.w*w1 + v2.w*w2 + v3.w*w3;
    }
    {
        const int l = l0 + 48;
        float4 v0 = *(const float4*)(base + (size_t)l * DD);
        float w0 = sp[l + 1];
        acc.x += v0.x*w0; acc.y += v0.y*w0; acc.z += v0.z*w0; acc.w += v0.w*w0;
    }
    red4[lg][c] = acc;
    __syncthreads();

    if (lg == 0) {
        float4 r0 = red4[0][c], r1 = red4[1][c], r2 = red4[2][c], r3 = red4[3][c];
        float4 f = *(const float4*)(g_fr + (size_t)b * DD + d0);
        float4 h = *(const float4*)(g_ho + (size_t)b * DD + d0);
        float p0 = sp[0];
        float4 o;
        o.x = r0.x + r1.x + r2.x + r3.x + f.x * p0 + h.x;
        o.y = r0.y + r1.y + r2.y + r3.y + f.y * p0 + h.y;
        o.z = r0.z + r1.z + r2.z + r3.z + f.z * p0 + h.z;
        o.w = r0.w + r1.w + r2.w + r3.w + f.w * p0 + h.w;
        *(float4*)(g_att + (size_t)b * DD + d0) = o;
    }
}

// ---------------- host launcher ----------------
extern "C" void kernel_launch(void* const* d_in, const int* in_sizes, int n_in,
                              void* d_out, int out_size)
{
    (void)in_sizes; (void)n_in; (void)out_size;
    const float* h_out = (const float*)d_in[0];
    const float* fake  = (const float*)d_in[1];
    const float* conv  = (const float*)d_in[2];
    const float* embed = (const float*)d_in[3];
    const float* W_fr  = (const float*)d_in[4];
    const float* b_fr  = (const float*)d_in[5];
    const float* W_fre = (const float*)d_in[6];
    const float* b_fre = (const float*)d_in[7];
    const float* W_ho  = (const float*)d_in[8];
    const float* b_ho  = (const float*)d_in[9];
    const float* W_hoe = (const float*)d_in[10];
    const float* b_hoe = (const float*)d_in[11];
    const float* W_a   = (const float*)d_in[12];
    const float* b_a   = (const float*)d_in[13];
    const float* W_h   = (const float*)d_in[14];
    const float* b_h   = (const float*)d_in[15];

    float *fr, *fre, *ho, *hoe, *att;
    cudaGetSymbolAddress((void**)&fr,  g_fr);
    cudaGetSymbolAddress((void**)&fre, g_fre);
    cudaGetSymbolAddress((void**)&ho,  g_ho);
    cudaGetSymbolAddress((void**)&hoe, g_hoe);
    cudaGetSymbolAddress((void**)&att, g_att);

    // stage 1: fr = relu(fake@W_fr^T + b), ho = tanh(h_out@W_ho^T + b)
    gemm_kernel<<<dim3(8, 1, 16), 256>>>(fake, W_fr, h_out, W_ho, 8, 128);
    combine8x2_kernel<<<dim3(256, 2), 128>>>(fr, b_fr, 1, ho, b_ho, 2);
    // stage 2: fre = fr@W_fre^T + b, hoe = ho@W_hoe^T + b
    gemm_kernel<<<dim3(8, 1, 16), 256>>>(fr, W_fre, ho, W_hoe, 8, 128);
    combine8x2_kernel<<<dim3(256, 2), 128>>>(fre, b_fre, 0, hoe, b_hoe, 0);
    // attention
    scores_kernel<<<dim3(25, BB), 256>>>(embed, W_a, b_a);
    wsum_kernel<<<dim3(4, BB), 256>>>(conv);
    // stage 3: h = tanh(att@W_h^T + b_h), ksplit=16 -> 128 blocks
    gemm_kernel<<<dim3(8, 1, 16), 256>>>(att, W_h, att, W_h, 16, 64);
    combine16_kernel<<<256, 128>>>((float*)d_out, b_h);
}

// round 15
// speedup vs baseline: 1.3909x; 1.1266x over previous
#include <cuda_runtime.h>

#define DD  1024
#define BB  128
#define LLn 196
#define LP1 197

// ---------------- scratch (no allocs allowed) ----------------
__device__ float g_fr [BB*DD];
__device__ float g_fre[BB*DD];
__device__ float g_ho [BB*DD];
__device__ float g_hoe[BB*DD];
__device__ float g_att[BB*DD];
__device__ float g_scores[BB*LP1];
__device__ float g_part[16][BB*DD];  // GEMM K-split partials

// ---------------- helpers ----------------
__device__ __forceinline__ float tanh_fast(float x) {
    float y;
    asm("tanh.approx.f32 %0, %1;" : "=f"(y) : "f"(x));
    return y;
}
__device__ __forceinline__ unsigned cvt_tf32(float x) {
    unsigned r;
    asm("cvt.rna.tf32.f32 %0, %1;" : "=r"(r) : "f"(x));
    return r;
}
__device__ __forceinline__ void mma_tf32(float* c, const unsigned* a, const unsigned* b) {
    asm volatile(
        "mma.sync.aligned.m16n8k8.row.col.f32.tf32.tf32.f32 "
        "{%0,%1,%2,%3}, {%4,%5,%6,%7}, {%8,%9}, {%0,%1,%2,%3};"
        : "+f"(c[0]), "+f"(c[1]), "+f"(c[2]), "+f"(c[3])
        : "r"(a[0]), "r"(a[1]), "r"(a[2]), "r"(a[3]), "r"(b[0]), "r"(b[1]));
}

// ---------------- GEMM partial: P = A[:,ks] @ W[:,ks]^T (tf32 tensor) ------
// BM=128 (full M), BN=128, BK=16, 256 threads = 8 warps (2m x 4n, 64x32 each).
// K-major smem As[k][m], Bs[k][n] (tf32 bits); fragment LDS conflict-free.
// grid (8, 1, z): prob = z / ks_per_prob, koff = (z % ks_per_prob) * klen.
__global__ void __launch_bounds__(256)
gemm_kernel(const float* __restrict__ A0, const float* __restrict__ W0,
            const float* __restrict__ A1, const float* __restrict__ W1,
            int ks_per_prob, int klen)
{
    const int bz = blockIdx.z;
    const float* A = (bz < ks_per_prob) ? A0 : A1;
    const float* W = (bz < ks_per_prob) ? W0 : W1;
    const int koff = (bz % ks_per_prob) * klen;
    float* P = g_part[bz];

    __shared__ unsigned As[2][16][136];       // [k][m], 128 + pad
    __shared__ unsigned Bs[2][16][136];       // [k][n], 128 + pad

    const int t  = threadIdx.x;
    const int bn = blockIdx.x << 7;

    const int lr = t >> 1, lc = (t & 1) << 3;     // loader: row 0..127, 2 float4
    const float* Ap = A + (size_t)lr * DD + koff + lc;
    const float* Wp = W + (size_t)(bn + lr) * DD + koff + lc;

    const int lane = t & 31;
    const int wid  = t >> 5;
    const int wm   = (wid >> 2) << 6;             // 0 / 64
    const int wn   = (wid & 3) << 5;              // 0 / 32 / 64 / 96
    const int fr_  = lane >> 2;                   // 0..7
    const int fc   = lane & 3;                    // 0..3

    float acc[4][4][4];                           // [mt][nt][4]
#pragma unroll
    for (int i = 0; i < 4; i++)
#pragma unroll
        for (int j = 0; j < 4; j++)
#pragma unroll
            for (int q = 0; q < 4; q++) acc[i][j][q] = 0.0f;

    float4 a0 = *(const float4*)Ap;
    float4 a1 = *(const float4*)(Ap + 4);
    float4 w0 = *(const float4*)Wp;
    float4 w1 = *(const float4*)(Wp + 4);

    {
        float a[8] = {a0.x,a0.y,a0.z,a0.w,a1.x,a1.y,a1.z,a1.w};
        float w[8] = {w0.x,w0.y,w0.z,w0.w,w1.x,w1.y,w1.z,w1.w};
#pragma unroll
        for (int i = 0; i < 8; i++) {
            As[0][lc+i][lr] = cvt_tf32(a[i]);
            Bs[0][lc+i][lr] = cvt_tf32(w[i]);
        }
    }
    __syncthreads();

    const int nkb = klen >> 4;
    int buf = 0;
#pragma unroll 1
    for (int kb = 0; kb < nkb; kb++) {
        if (kb < nkb - 1) {
            a0 = *(const float4*)(Ap + (kb + 1) * 16);
            a1 = *(const float4*)(Ap + (kb + 1) * 16 + 4);
            w0 = *(const float4*)(Wp + (kb + 1) * 16);
            w1 = *(const float4*)(Wp + (kb + 1) * 16 + 4);
        }
#pragma unroll
        for (int k0 = 0; k0 < 16; k0 += 8) {
            unsigned af[4][4];
#pragma unroll
            for (int mt = 0; mt < 4; mt++) {
                const int m = wm + (mt << 4) + fr_;
                af[mt][0] = As[buf][k0 + fc][m];
                af[mt][1] = As[buf][k0 + fc][m + 8];
                af[mt][2] = As[buf][k0 + fc + 4][m];
                af[mt][3] = As[buf][k0 + fc + 4][m + 8];
            }
            unsigned bf[4][2];
#pragma unroll
            for (int nt = 0; nt < 4; nt++) {
                const int n = wn + (nt << 3) + fr_;
                bf[nt][0] = Bs[buf][k0 + fc][n];
                bf[nt][1] = Bs[buf][k0 + fc + 4][n];
            }
#pragma unroll
            for (int mt = 0; mt < 4; mt++)
#pragma unroll
                for (int nt = 0; nt < 4; nt++)
                    mma_tf32(acc[mt][nt], af[mt], bf[nt]);
        }
        if (kb < nkb - 1) {
            const int nb = buf ^ 1;
            float a[8] = {a0.x,a0.y,a0.z,a0.w,a1.x,a1.y,a1.z,a1.w};
            float w[8] = {w0.x,w0.y,w0.z,w0.w,w1.x,w1.y,w1.z,w1.w};
#pragma unroll
            for (int i = 0; i < 8; i++) {
                As[nb][lc+i][lr] = cvt_tf32(a[i]);
                Bs[nb][lc+i][lr] = cvt_tf32(w[i]);
            }
            __syncthreads();
            buf = nb;
        }
    }

    // epilogue: c0,c1 -> row wm+mt*16+fr_, cols 2*fc,2*fc+1 ; c2,c3 -> row+8
#pragma unroll
    for (int mt = 0; mt < 4; mt++) {
        float* r0 = P + (size_t)(wm + (mt << 4) + fr_) * DD + bn;
        float* r1 = r0 + 8 * DD;
#pragma unroll
        for (int nt = 0; nt < 4; nt++) {
            const int col = wn + (nt << 3) + (fc << 1);
            *(float2*)(r0 + col) = make_float2(acc[mt][nt][0], acc[mt][nt][1]);
            *(float2*)(r1 + col) = make_float2(acc[mt][nt][2], acc[mt][nt][3]);
        }
    }
}

// ---------------- combine8x2: dst = act(sum of 8 partials + bias), 2 problems ----
__global__ void __launch_bounds__(128)
combine8x2_kernel(float* __restrict__ dst0, const float* __restrict__ bias0, int act0,
                  float* __restrict__ dst1, const float* __restrict__ bias1, int act1)
{
    const int p = blockIdx.y;
    float* dst        = p ? dst1  : dst0;
    const float* bias = p ? bias1 : bias0;
    const int act     = p ? act1  : act0;

    const int idx = blockIdx.x * 128 + threadIdx.x;
    float4 bi = ((const float4*)bias)[idx & 255];
    float s[4] = { bi.x, bi.y, bi.z, bi.w };
#pragma unroll
    for (int q = 0; q < 8; q++) {
        float4 a = ((const float4*)g_part[8*p + q])[idx];
        s[0] += a.x; s[1] += a.y; s[2] += a.z; s[3] += a.w;
    }
    if (act == 1) {
#pragma unroll
        for (int j = 0; j < 4; j++) s[j] = fmaxf(s[j], 0.0f);
    } else if (act == 2) {
#pragma unroll
        for (int j = 0; j < 4; j++) s[j] = tanhf(s[j]);
    }
    ((float4*)dst)[idx] = make_float4(s[0], s[1], s[2], s[3]);
}

// ---------------- combine16: dst = tanh(sum of 16 partials + bias) ----------------
__global__ void __launch_bounds__(128)
combine16_kernel(float* __restrict__ dst, const float* __restrict__ bias)
{
    const int idx = blockIdx.x * 128 + threadIdx.x;
    float4 bi = ((const float4*)bias)[idx & 255];
    float s[4] = { bi.x, bi.y, bi.z, bi.w };
#pragma unroll
    for (int q = 0; q < 16; q++) {
        float4 a = ((const float4*)g_part[q])[idx];
        s[0] += a.x; s[1] += a.y; s[2] += a.z; s[3] += a.w;
    }
    ((float4*)dst)[idx] = make_float4(tanhf(s[0]), tanhf(s[1]),
                                      tanhf(s[2]), tanhf(s[3]));
}

// ---------------- scores[b,l] = Wa . tanh(E[b,l,:] + hoe[b,:]) + ba ----------------
__global__ void __launch_bounds__(256)
scores_kernel(const float* __restrict__ embed,
              const float* __restrict__ Wa, const float* __restrict__ ba)
{
    const int b    = blockIdx.y;
    const int t    = threadIdx.x;
    const int w    = t >> 5;
    const int lane = t & 31;
    const int l    = blockIdx.x * 8 + w;
    if (l >= LP1) return;

    const float* row  = (l == 0) ? (g_fre + (size_t)b * DD)
                                 : (embed + ((size_t)b * LLn + (l - 1)) * DD);
    const float* hrow = g_hoe + (size_t)b * DD;

    float acc = 0.0f;
#pragma unroll
    for (int p = 0; p < 8; p++) {
        const int d = p * 128 + lane * 4;
        float4 e = *(const float4*)(row  + d);
        float4 h = *(const float4*)(hrow + d);
        float4 v = *(const float4*)(Wa   + d);
        acc = fmaf(tanh_fast(e.x + h.x), v.x, acc);
        acc = fmaf(tanh_fast(e.y + h.y), v.y, acc);
        acc = fmaf(tanh_fast(e.z + h.z), v.z, acc);
        acc = fmaf(tanh_fast(e.w + h.w), v.w, acc);
    }
#pragma unroll
    for (int o = 16; o; o >>= 1) acc += __shfl_xor_sync(0xffffffffu, acc, o);
    if (lane == 0) g_scores[b * LP1 + l] = acc + ba[0];
}

// ---------------- fused softmax + weighted sum ----------------
__global__ void __launch_bounds__(256)
wsum_kernel(const float* __restrict__ conv)
{
    const int s = blockIdx.x, b = blockIdx.y, t = threadIdx.x;
    __shared__ float  sp[LP1];
    __shared__ float  red[8];
    __shared__ float4 red4[4][64];

    float v = (t < LP1) ? g_scores[b * LP1 + t] : -3.4e38f;
    float m = v;
#pragma unroll
    for (int o = 16; o; o >>= 1) m = fmaxf(m, __shfl_xor_sync(0xffffffffu, m, o));
    if ((t & 31) == 0) red[t >> 5] = m;
    __syncthreads();
    float mx = red[0];
#pragma unroll
    for (int i = 1; i < 8; i++) mx = fmaxf(mx, red[i]);
    __syncthreads();

    float e = (t < LP1) ? expf(v - mx) : 0.0f;
    float su = e;
#pragma unroll
    for (int o = 16; o; o >>= 1) su += __shfl_xor_sync(0xffffffffu, su, o);
    if ((t & 31) == 0) red[t >> 5] = su;
    __syncthreads();
    float tot = red[0] + red[1] + red[2] + red[3]
              + red[4] + red[5] + red[6] + red[7];
    if (t < LP1) sp[t] = e / tot;
    __syncthreads();

    const int c  = t & 63;
    const int lg = t >> 6;
    const int d0 = (s << 8) + (c << 2);
    const float* base = conv + (size_t)b * LLn * DD + d0;

    float4 acc = make_float4(0.f, 0.f, 0.f, 0.f);
    const int l0 = lg * 49;
#pragma unroll 1
    for (int u = 0; u < 12; u++) {
        const int l = l0 + (u << 2);
        float4 v0 = *(const float4*)(base + (size_t)(l + 0) * DD);
        float4 v1 = *(const float4*)(base + (size_t)(l + 1) * DD);
        float4 v2 = *(const float4*)(base + (size_t)(l + 2) * DD);
        float4 v3 = *(const float4*)(base + (size_t)(l + 3) * DD);
        float w0 = sp[l + 1], w1 = sp[l + 2], w2 = sp[l + 3], w3 = sp[l + 4];
        acc.x += v0.x*w0 + v1.x*w1 + v2.x*w2 + v3.x*w3;
        acc.y += v0.y*w0 + v1.y*w1 + v2.y*w2 + v3.y*w3;
        acc.z += v0.z*w0 + v1.z*w1 + v2.z*w2 + v3.z*w3;
        acc.w += v0.w*w0 + v1.w*w1 + v2.w*w2 + v3.w*w3;
    }
    {
        const int l = l0 + 48;
        float4 v0 = *(const float4*)(base + (size_t)l * DD);
        float w0 = sp[l + 1];
        acc.x += v0.x*w0; acc.y += v0.y*w0; acc.z += v0.z*w0; acc.w += v0.w*w0;
    }
    red4[lg][c] = acc;
    __syncthreads();

    if (lg == 0) {
        float4 r0 = red4[0][c], r1 = red4[1][c], r2 = red4[2][c], r3 = red4[3][c];
        float4 f = *(const float4*)(g_fr + (size_t)b * DD + d0);
        float4 h = *(const float4*)(g_ho + (size_t)b * DD + d0);
        float p0 = sp[0];
        float4 o;
        o.x = r0.x + r1.x + r2.x + r3.x + f.x * p0 + h.x;
        o.y = r0.y + r1.y + r2.y + r3.y + f.y * p0 + h.y;
        o.z = r0.z + r1.z + r2.z + r3.z + f.z * p0 + h.z;
        o.w = r0.w + r1.w + r2.w + r3.w + f.w * p0 + h.w;
        *(float4*)(g_att + (size_t)b * DD + d0) = o;
    }
}

// ---------------- host launcher ----------------
extern "C" void kernel_launch(void* const* d_in, const int* in_sizes, int n_in,
                              void* d_out, int out_size)
{
    (void)in_sizes; (void)n_in; (void)out_size;
    const float* h_out = (const float*)d_in[0];
    const float* fake  = (const float*)d_in[1];
    const float* conv  = (const float*)d_in[2];
    const float* embed = (const float*)d_in[3];
    const float* W_fr  = (const float*)d_in[4];
    const float* b_fr  = (const float*)d_in[5];
    const float* W_fre = (const float*)d_in[6];
    const float* b_fre = (const float*)d_in[7];
    const float* W_ho  = (const float*)d_in[8];
    const float* b_ho  = (const float*)d_in[9];
    const float* W_hoe = (const float*)d_in[10];
    const float* b_hoe = (const float*)d_in[11];
    const float* W_a   = (const float*)d_in[12];
    const float* b_a   = (const float*)d_in[13];
    const float* W_h   = (const float*)d_in[14];
    const float* b_h   = (const float*)d_in[15];

    float *fr, *fre, *ho, *hoe, *att;
    cudaGetSymbolAddress((void**)&fr,  g_fr);
    cudaGetSymbolAddress((void**)&fre, g_fre);
    cudaGetSymbolAddress((void**)&ho,  g_ho);
    cudaGetSymbolAddress((void**)&hoe, g_hoe);
    cudaGetSymbolAddress((void**)&att, g_att);

    // stage 1: fr = relu(fake@W_fr^T + b), ho = tanh(h_out@W_ho^T + b)
    gemm_kernel<<<dim3(8, 1, 16), 256>>>(fake, W_fr, h_out, W_ho, 8, 128);
    combine8x2_kernel<<<dim3(256, 2), 128>>>(fr, b_fr, 1, ho, b_ho, 2);
    // stage 2: fre = fr@W_fre^T + b, hoe = ho@W_hoe^T + b
    gemm_kernel<<<dim3(8, 1, 16), 256>>>(fr, W_fre, ho, W_hoe, 8, 128);
    combine8x2_kernel<<<dim3(256, 2), 128>>>(fre, b_fre, 0, hoe, b_hoe, 0);
    // attention
    scores_kernel<<<dim3(25, BB), 256>>>(embed, W_a, b_a);
    wsum_kernel<<<dim3(4, BB), 256>>>(conv);
    // stage 3: h = tanh(att@W_h^T + b_h), ksplit=16 -> 128 blocks
    gemm_kernel<<<dim3(8, 1, 16), 256>>>(att, W_h, att, W_h, 16, 64);
    combine16_kernel<<<256, 128>>>((float*)d_out, b_h);
}